// round 16
// baseline (speedup 1.0000x reference)
#include <cuda_runtime.h>
#include <cuda_bf16.h>
#include <math.h>

#define U_DIM 4096
#define T_DIM 200
#define K_DIM 64
#define Q_DIM 10000
#define H_DIM 128

typedef unsigned long long u64;

// Scratch (device globals; no allocation in kernel_launch)
__device__ float4 d_tab4[2 * Q_DIM];             // (mu, r, ts, ts*td) per (q,resp)
__device__ unsigned char d_kcq[Q_DIM];           // kc per question

__device__ __forceinline__ float gelu_exact(float x) {
    return 0.5f * x * (1.0f + erff(x * 0.70710678118654752440f));
}

__device__ __forceinline__ u64 pack2(float lo, float hi) {
    u64 r; asm("mov.b64 %0, {%1, %2};" : "=l"(r) : "f"(lo), "f"(hi)); return r;
}
__device__ __forceinline__ void unpack2(u64 v, float& lo, float& hi) {
    asm("mov.b64 {%0, %1}, %2;" : "=f"(lo), "=f"(hi) : "l"(v));
}
__device__ __forceinline__ u64 fma2(u64 a, u64 b, u64 c) {
    u64 d; asm("fma.rn.f32x2 %0, %1, %2, %3;" : "=l"(d) : "l"(a), "l"(b), "l"(c));
    return d;
}

// ---------------------------------------------------------------------------
// Kernel A: per-(q,resp) MLP table + kc_of_q. One warp per 8 tasks
// (4 questions x resp {0,1}), 4 warps/block (32KB static smem).
// Layer-1 h stored DUPLICATED in smem so layer-2 fetches the FFMA2 operand
// (h_i,h_i) with ONE uniform LDS.64. W2 loads DOUBLE-BUFFERED: next base's
// LDG.128s issue before the current FMA block (kills the per-iteration
// load-dependency stall). kmap is int32-upconverted bool.
// ---------------------------------------------------------------------------
__global__ void __launch_bounds__(128) mlp_table_kernel(
    const float* __restrict__ dmu, const float* __restrict__ smu,
    const int* __restrict__ kmap,
    const float* __restrict__ W1, const float* __restrict__ b1,
    const float* __restrict__ W2, const float* __restrict__ b2,
    const float* __restrict__ W3, const float* __restrict__ b3)
{
    __shared__ float sh2[4][8 * 2 * H_DIM];   // [warp][task*256 + 2*unit + {0,1}]

    const int lane = threadIdx.x & 31;
    const int wid  = threadIdx.x >> 5;
    const int gw = (blockIdx.x * blockDim.x + threadIdx.x) >> 5;
    if (gw >= Q_DIM / 4) return;
    const int q0 = gw * 4;

    // ---- kc_of_q via ballot: warp owns questions q0..q0+3 ----
    #pragma unroll
    for (int j = 0; j < 4; j++) {
        int q = q0 + j;
        int vlo = kmap[q * K_DIM + lane];
        int vhi = kmap[q * K_DIM + 32 + lane];
        unsigned lo = __ballot_sync(0xFFFFFFFFu, vlo != 0);
        unsigned hi = __ballot_sync(0xFFFFFFFFu, vhi != 0);
        if (lane == 0) {
            int kc = lo ? (__ffs(lo) - 1) : (32 + __ffs(hi) - 1);
            d_kcq[q] = (unsigned char)kc;
        }
    }

    float x0[4], x1[4];
    #pragma unroll
    for (int j = 0; j < 4; j++) { x0[j] = dmu[q0 + j]; x1[j] = smu[q0 + j]; }

    // ---- layer 1: units 4*lane..4*lane+3; task tt: q=q0+(tt>>1), resp=tt&1 ----
    const float4 w10 = *(const float4*)(W1 + 0 * H_DIM + 4 * lane);
    const float4 w11 = *(const float4*)(W1 + 1 * H_DIM + 4 * lane);
    const float4 w12 = *(const float4*)(W1 + 2 * H_DIM + 4 * lane);
    const float4 b1v = *(const float4*)(b1 + 4 * lane);
    float r0[4] = {w10.x, w10.y, w10.z, w10.w};
    float r1[4] = {w11.x, w11.y, w11.z, w11.w};
    float r2[4] = {w12.x, w12.y, w12.z, w12.w};
    float bb[4] = {b1v.x, b1v.y, b1v.z, b1v.w};

    #pragma unroll
    for (int j = 0; j < 4; j++) {
        float h0[4], h1[4];
        #pragma unroll
        for (int e = 0; e < 4; e++) {
            float pre = fmaf(x0[j], r0[e], fmaf(x1[j], r1[e], bb[e]));
            h0[e] = gelu_exact(pre);
            h1[e] = gelu_exact(pre + r2[e]);
        }
        float* p0 = &sh2[wid][(2 * j) * 2 * H_DIM + 8 * lane];
        float* p1 = &sh2[wid][(2 * j + 1) * 2 * H_DIM + 8 * lane];
        *(float4*)(p0)     = make_float4(h0[0], h0[0], h0[1], h0[1]);
        *(float4*)(p0 + 4) = make_float4(h0[2], h0[2], h0[3], h0[3]);
        *(float4*)(p1)     = make_float4(h1[0], h1[0], h1[1], h1[1]);
        *(float4*)(p1 + 4) = make_float4(h1[2], h1[2], h1[3], h1[3]);
    }
    __syncwarp();

    // ---- layer 2: 128x128 dense, FFMA2, double-buffered W2 loads ----
    const float4 b2v = *(const float4*)(b2 + 4 * lane);
    u64 accp[8][2];
    #pragma unroll
    for (int t = 0; t < 8; t++) {
        accp[t][0] = pack2(b2v.x, b2v.y);
        accp[t][1] = pack2(b2v.z, b2v.w);
    }
    ulonglong2 wv[4];
    #pragma unroll
    for (int ii = 0; ii < 4; ii++)
        wv[ii] = *(const ulonglong2*)(W2 + ii * H_DIM + 4 * lane);

    #pragma unroll 4
    for (int base = 0; base < 32; base++) {
        u64 w2p[4][2];
        #pragma unroll
        for (int ii = 0; ii < 4; ii++) {
            w2p[ii][0] = wv[ii].x;
            w2p[ii][1] = wv[ii].y;
        }
        if (base < 31) {
            #pragma unroll
            for (int ii = 0; ii < 4; ii++)
                wv[ii] = *(const ulonglong2*)(W2 + ((base + 1) * 4 + ii) * H_DIM
                                              + 4 * lane);
        }
        #pragma unroll
        for (int t = 0; t < 8; t++) {
            const float* hb = &sh2[wid][t * 2 * H_DIM + 8 * base]; // uniform addr
            #pragma unroll
            for (int ii = 0; ii < 4; ii++) {
                u64 hp = *(const u64*)(hb + 2 * ii);   // (h_i, h_i) via LDS.64
                accp[t][0] = fma2(hp, w2p[ii][0], accp[t][0]);
                accp[t][1] = fma2(hp, w2p[ii][1], accp[t][1]);
            }
        }
    }
    float h2[8][4];
    #pragma unroll
    for (int t = 0; t < 8; t++) {
        float a0, a1, a2, a3;
        unpack2(accp[t][0], a0, a1);
        unpack2(accp[t][1], a2, a3);
        h2[t][0] = gelu_exact(a0);
        h2[t][1] = gelu_exact(a1);
        h2[t][2] = gelu_exact(a2);
        h2[t][3] = gelu_exact(a3);
    }

    // ---- layer 3: 128 -> 2, warp reduce ----
    const float4 w3a = *(const float4*)(W3 + 8 * lane);
    const float4 w3b = *(const float4*)(W3 + 8 * lane + 4);
    const float b30 = b3[0], b31 = b3[1];

    float o0[8], o1[8];
    #pragma unroll
    for (int t = 0; t < 8; t++) {
        o0[t] = fmaf(h2[t][0], w3a.x, fmaf(h2[t][1], w3a.z,
                fmaf(h2[t][2], w3b.x, h2[t][3] * w3b.z)));
        o1[t] = fmaf(h2[t][0], w3a.y, fmaf(h2[t][1], w3a.w,
                fmaf(h2[t][2], w3b.y, h2[t][3] * w3b.w)));
    }
    #pragma unroll
    for (int off = 16; off; off >>= 1) {
        #pragma unroll
        for (int t = 0; t < 8; t++) {
            o0[t] += __shfl_xor_sync(0xFFFFFFFFu, o0[t], off);
            o1[t] += __shfl_xor_sync(0xFFFFFFFFu, o1[t], off);
        }
    }
    if (lane == 0) {
        #pragma unroll
        for (int t = 0; t < 8; t++) {
            float mu = gelu_exact(o0[t] + b30);
            float lv = gelu_exact(o1[t] + b31);
            float s = fmaxf(expf(0.5f * lv), 1e-8f);
            float inv = 1.0f / s;
            int j = t >> 1;
            float ts = x1[j], td = x0[j];
            d_tab4[8 * gw + t] = make_float4(mu, inv * inv, ts, ts * td);
        }
    }
}

// ---------------------------------------------------------------------------
// Kernel B: FUSED backward Mobius scan + forward KC scan, warp-per-user.
// Phase 2 uses a SIMD byte-match fast-skip: one __vcmpeq4 per 4-trial group
// flags this lane's owned trials; ~77% of groups cost ~5 instr (no match).
// Matches popped lowest-byte-first (ascending t; kc chains are per-lane
// independent so cross-lane order is irrelevant).
// ---------------------------------------------------------------------------
__global__ void __launch_bounds__(256) scan_kernel(
    const int* __restrict__ q_id, const int* __restrict__ resp,
    float* __restrict__ out)
{
    const int lane = threadIdx.x & 31;
    const int wid  = threadIdx.x >> 5;
    const int u = blockIdx.x * 8 + wid;
    const int base = lane * 7;

    __shared__ float2 sbc[8][T_DIM];         // (b, c); m overwrites .x
    __shared__ unsigned int skcw[8][56];     // kc bytes (224 padded)
    __shared__ int sqr[8][224];              // 2*q+rs, then logits (reused)

    unsigned char* skc = (unsigned char*)&skcw[wid][0];

    // ---- phase 0: coalesced q/resp -> combined index in smem ----
    #pragma unroll
    for (int j = 0; j < 7; j++) {
        int t = j * 32 + lane;
        if (t < T_DIM) {
            int q  = q_id[u * T_DIM + t];
            int rs = resp[u * T_DIM + t];
            sqr[wid][t] = 2 * q + rs;
        }
    }
    __syncwarp();

    // ---- phase 1: gather packed trial records for owned segment ----
    float mu[7], rr[7], tsv[7], tdd[7];
    int kcv[7];
    #pragma unroll
    for (int j = 0; j < 7; j++) {
        int t = base + j;
        if (t < T_DIM) {
            int idx = sqr[wid][t];
            float4 f = d_tab4[idx];
            mu[j] = f.x; rr[j] = f.y; tsv[j] = f.z; tdd[j] = f.w;
            kcv[j] = d_kcq[idx >> 1];
        } else {
            mu[j] = 0.0f; rr[j] = 0.0f; tsv[j] = 0.0f; tdd[j] = 0.0f; kcv[j] = 0;
        }
    }

    // ---- local product S = M_base * ... * M_{base+6} ----
    float m00 = 1.0f, m01 = 0.0f, m10 = 0.0f, m11 = 1.0f;
    float m20 = 0.0f, m21 = 0.0f, m22 = 1.0f;
    #pragma unroll
    for (int j = 6; j >= 0; j--) {
        if (base + j < T_DIM) {
            float a = 2.0f + rr[j];
            float g = rr[j] * mu[j];
            float n00 = m10,                n01 = m11;
            float n10 = fmaf(a, m10, -m00);
            float n11 = fmaf(a, m11, -m01);
            float n20 = fmaf(g, m10, m20);
            float n21 = fmaf(g, m11, m21);
            m00 = n00; m01 = n01; m10 = n10; m11 = n11;
            m20 = n20; m21 = n21;
        }
    }

    // ---- inclusive suffix scan (renormalized; q>0 invariant) ----
    #pragma unroll
    for (int d = 1; d < 32; d <<= 1) {
        float b00 = __shfl_down_sync(0xFFFFFFFFu, m00, d);
        float b01 = __shfl_down_sync(0xFFFFFFFFu, m01, d);
        float b10 = __shfl_down_sync(0xFFFFFFFFu, m10, d);
        float b11 = __shfl_down_sync(0xFFFFFFFFu, m11, d);
        float b20 = __shfl_down_sync(0xFFFFFFFFu, m20, d);
        float b21 = __shfl_down_sync(0xFFFFFFFFu, m21, d);
        float b22 = __shfl_down_sync(0xFFFFFFFFu, m22, d);
        if (lane + d < 32) {
            float c00 = fmaf(m00, b00, m01 * b10);
            float c01 = fmaf(m00, b01, m01 * b11);
            float c10 = fmaf(m10, b00, m11 * b10);
            float c11 = fmaf(m10, b01, m11 * b11);
            float c20 = fmaf(m20, b00, fmaf(m21, b10, m22 * b20));
            float c21 = fmaf(m20, b01, fmaf(m21, b11, m22 * b21));
            float c22 = m22 * b22;
            float s = __fdividef(1.0f, fabsf(c10) + fabsf(c11) + 1e-30f);
            m00 = c00 * s; m01 = c01 * s;
            m10 = c10 * s; m11 = c11 * s;
            m20 = c20 * s; m21 = c21 * s; m22 = c22 * s;
        }
    }

    // ---- exclusive carry: P_l = T_{l+1}; lane 31 -> identity ----
    float p00 = __shfl_down_sync(0xFFFFFFFFu, m00, 1);
    float p01 = __shfl_down_sync(0xFFFFFFFFu, m01, 1);
    float p10 = __shfl_down_sync(0xFFFFFFFFu, m10, 1);
    float p11 = __shfl_down_sync(0xFFFFFFFFu, m11, 1);
    float p20 = __shfl_down_sync(0xFFFFFFFFu, m20, 1);
    float p21 = __shfl_down_sync(0xFFFFFFFFu, m21, 1);
    if (lane == 31) {
        p00 = 1.0f; p01 = 0.0f; p10 = 0.0f; p11 = 1.0f; p20 = 0.0f; p21 = 0.0f;
    }

    float pp = p00 + p01;
    float qq = p10 + p11;
    float ww = p20 + p21;
    float invq = __fdividef(1.0f, qq);
    float b = pp * invq;
    float c = ww * invq;

    // ---- local replay (exact reference arithmetic), write to SMEM ----
    #pragma unroll
    for (int j = 6; j >= 0; j--) {
        int t = base + j;
        if (t < T_DIM) {
            float bn = __fdividef(1.0f, 2.0f + rr[j] - b);
            c = bn * fmaf(rr[j], mu[j], c);
            b = bn;
            sbc[wid][t] = make_float2(b, c);
            skc[t] = (unsigned char)kcv[j];
        }
    }
    __syncwarp();

    // ---- phase 2: forward scan, register KC state, vcmpeq fast-skip ----
    float s0 = 0.0f, s1 = 0.0f;
    const unsigned lrep = lane * 0x01010101u;
    #pragma unroll 5
    for (int g = 0; g < T_DIM / 4; g++) {
        unsigned kw = skcw[wid][g];                      // uniform LDS.32
        unsigned match = __vcmpeq4(kw & 0x1F1F1F1Fu, lrep);
        while (match) {
            int byte = (__ffs(match) - 1) >> 3;          // lowest t first
            int t = 4 * g + byte;
            int kj = (kw >> (8 * byte)) & 0xFF;
            float2 bc = sbc[wid][t];
            float s = (kj & 32) ? s1 : s0;
            float m = fmaf(bc.x, s, bc.y);
            if (kj & 32) s1 = m; else s0 = m;
            sbc[wid][t].x = m;                           // m overwrites b (dead)
            match &= ~(0xFFu << (8 * byte));
        }
    }
    __syncwarp();

    // ---- epilogue: logits staged to smem (sqr is dead), stored coalesced ----
    float* slog = (float*)&sqr[wid][0];
    #pragma unroll
    for (int j = 0; j < 7; j++) {
        int t = base + j;
        if (t < T_DIM) {
            float m = sbc[wid][t].x;
            slog[t] = fmaf(tsv[j], m, -tdd[j]);  // ts*m - ts*td
        }
    }
    __syncwarp();
    #pragma unroll
    for (int j = 0; j < 7; j++) {
        int t = j * 32 + lane;
        if (t < T_DIM) out[u * T_DIM + t] = slog[t];
    }

    // last_ability_kc: (U, K); lane owns k=lane (s0) and k=lane+32 (s1)
    float* o2 = out + (size_t)U_DIM * T_DIM + (size_t)u * K_DIM;
    o2[lane] = s0;
    o2[32 + lane] = s1;
}

// ---------------------------------------------------------------------------
// Launch
// ---------------------------------------------------------------------------
extern "C" void kernel_launch(void* const* d_in, const int* in_sizes, int n_in,
                              void* d_out, int out_size)
{
    // metadata order: mask, q_id, kmap, resp, diff_mu, disc_mu, W1,b1,W2,b2,W3,b3
    const int* q_id = (const int*)d_in[1];
    const int* kmap = (const int*)d_in[2];
    const int* resp = (const int*)d_in[3];
    const float* dmu = (const float*)d_in[4];
    const float* smu = (const float*)d_in[5];
    const float* W1 = (const float*)d_in[6];
    const float* b1 = (const float*)d_in[7];
    const float* W2 = (const float*)d_in[8];
    const float* b2 = (const float*)d_in[9];
    const float* W3 = (const float*)d_in[10];
    const float* b3 = (const float*)d_in[11];
    float* out = (float*)d_out;

    mlp_table_kernel<<<(Q_DIM / 4 + 3) / 4, 128>>>(dmu, smu, kmap,
                                                   W1, b1, W2, b2, W3, b3);
    scan_kernel<<<U_DIM / 8, 256>>>(q_id, resp, out);
}

// round 17
// speedup vs baseline: 1.1255x; 1.1255x over previous
#include <cuda_runtime.h>
#include <cuda_bf16.h>
#include <math.h>

#define U_DIM 4096
#define T_DIM 200
#define K_DIM 64
#define Q_DIM 10000
#define H_DIM 128

typedef unsigned long long u64;

// Scratch (device globals; no allocation in kernel_launch)
// d_tab4: (mu, r, ts_enc, ts*td) per (q,resp); kc embedded in low 6 mantissa
// bits of ts_enc (rel perturbation <= 2^-18, only affects final logit term).
__device__ float4 d_tab4[2 * Q_DIM];

__device__ __forceinline__ float gelu_exact(float x) {
    return 0.5f * x * (1.0f + erff(x * 0.70710678118654752440f));
}

__device__ __forceinline__ u64 pack2(float lo, float hi) {
    u64 r; asm("mov.b64 %0, {%1, %2};" : "=l"(r) : "f"(lo), "f"(hi)); return r;
}
__device__ __forceinline__ void unpack2(u64 v, float& lo, float& hi) {
    asm("mov.b64 {%0, %1}, %2;" : "=f"(lo), "=f"(hi) : "l"(v));
}
__device__ __forceinline__ u64 fma2(u64 a, u64 b, u64 c) {
    u64 d; asm("fma.rn.f32x2 %0, %1, %2, %3;" : "=l"(d) : "l"(a), "l"(b), "l"(c));
    return d;
}

// ---------------------------------------------------------------------------
// Kernel A: per-(q,resp) MLP table + kc_of_q. One warp per 8 tasks
// (4 questions x resp {0,1}), 4 warps/block (32KB static smem).
// Layer-1 h stored DUPLICATED in smem so layer-2 fetches the FFMA2 operand
// (h_i,h_i) with ONE uniform LDS.64 (no MOV packs). NO W2 double-buffering
// (R16 showed it regresses via register pressure). kc computed via ballot
// and embedded into ts_enc. kmap is int32-upconverted bool.
// ---------------------------------------------------------------------------
__global__ void __launch_bounds__(128) mlp_table_kernel(
    const float* __restrict__ dmu, const float* __restrict__ smu,
    const int* __restrict__ kmap,
    const float* __restrict__ W1, const float* __restrict__ b1,
    const float* __restrict__ W2, const float* __restrict__ b2,
    const float* __restrict__ W3, const float* __restrict__ b3)
{
    __shared__ float sh2[4][8 * 2 * H_DIM];   // [warp][task*256 + 2*unit + {0,1}]

    const int lane = threadIdx.x & 31;
    const int wid  = threadIdx.x >> 5;
    const int gw = (blockIdx.x * blockDim.x + threadIdx.x) >> 5;
    if (gw >= Q_DIM / 4) return;
    const int q0 = gw * 4;

    // ---- kc_of_q via ballot: warp owns questions q0..q0+3 ----
    // ballot results are warp-uniform -> every lane keeps kc for all 4 q's
    int kcq[4];
    #pragma unroll
    for (int j = 0; j < 4; j++) {
        int q = q0 + j;
        int vlo = kmap[q * K_DIM + lane];
        int vhi = kmap[q * K_DIM + 32 + lane];
        unsigned lo = __ballot_sync(0xFFFFFFFFu, vlo != 0);
        unsigned hi = __ballot_sync(0xFFFFFFFFu, vhi != 0);
        kcq[j] = lo ? (__ffs(lo) - 1) : (32 + __ffs(hi) - 1);
    }

    float x0[4], x1[4];
    #pragma unroll
    for (int j = 0; j < 4; j++) { x0[j] = dmu[q0 + j]; x1[j] = smu[q0 + j]; }

    // ---- layer 1: units 4*lane..4*lane+3; task tt: q=q0+(tt>>1), resp=tt&1 ----
    const float4 w10 = *(const float4*)(W1 + 0 * H_DIM + 4 * lane);
    const float4 w11 = *(const float4*)(W1 + 1 * H_DIM + 4 * lane);
    const float4 w12 = *(const float4*)(W1 + 2 * H_DIM + 4 * lane);
    const float4 b1v = *(const float4*)(b1 + 4 * lane);
    float r0[4] = {w10.x, w10.y, w10.z, w10.w};
    float r1[4] = {w11.x, w11.y, w11.z, w11.w};
    float r2[4] = {w12.x, w12.y, w12.z, w12.w};
    float bb[4] = {b1v.x, b1v.y, b1v.z, b1v.w};

    #pragma unroll
    for (int j = 0; j < 4; j++) {
        float h0[4], h1[4];
        #pragma unroll
        for (int e = 0; e < 4; e++) {
            float pre = fmaf(x0[j], r0[e], fmaf(x1[j], r1[e], bb[e]));
            h0[e] = gelu_exact(pre);
            h1[e] = gelu_exact(pre + r2[e]);
        }
        float* p0 = &sh2[wid][(2 * j) * 2 * H_DIM + 8 * lane];
        float* p1 = &sh2[wid][(2 * j + 1) * 2 * H_DIM + 8 * lane];
        *(float4*)(p0)     = make_float4(h0[0], h0[0], h0[1], h0[1]);
        *(float4*)(p0 + 4) = make_float4(h0[2], h0[2], h0[3], h0[3]);
        *(float4*)(p1)     = make_float4(h1[0], h1[0], h1[1], h1[1]);
        *(float4*)(p1 + 4) = make_float4(h1[2], h1[2], h1[3], h1[3]);
    }
    __syncwarp();

    // ---- layer 2: 128x128 dense, FFMA2, duplicated-h uniform LDS.64 ----
    const float4 b2v = *(const float4*)(b2 + 4 * lane);
    u64 accp[8][2];
    #pragma unroll
    for (int t = 0; t < 8; t++) {
        accp[t][0] = pack2(b2v.x, b2v.y);
        accp[t][1] = pack2(b2v.z, b2v.w);
    }
    #pragma unroll 2
    for (int base = 0; base < 32; base++) {
        u64 w2p[4][2];
        #pragma unroll
        for (int ii = 0; ii < 4; ii++) {
            const ulonglong2 wv =
                *(const ulonglong2*)(W2 + (base * 4 + ii) * H_DIM + 4 * lane);
            w2p[ii][0] = wv.x;
            w2p[ii][1] = wv.y;
        }
        #pragma unroll
        for (int t = 0; t < 8; t++) {
            const float* hb = &sh2[wid][t * 2 * H_DIM + 8 * base]; // uniform addr
            #pragma unroll
            for (int ii = 0; ii < 4; ii++) {
                u64 hp = *(const u64*)(hb + 2 * ii);   // (h_i, h_i) via LDS.64
                accp[t][0] = fma2(hp, w2p[ii][0], accp[t][0]);
                accp[t][1] = fma2(hp, w2p[ii][1], accp[t][1]);
            }
        }
    }
    float h2[8][4];
    #pragma unroll
    for (int t = 0; t < 8; t++) {
        float a0, a1, a2, a3;
        unpack2(accp[t][0], a0, a1);
        unpack2(accp[t][1], a2, a3);
        h2[t][0] = gelu_exact(a0);
        h2[t][1] = gelu_exact(a1);
        h2[t][2] = gelu_exact(a2);
        h2[t][3] = gelu_exact(a3);
    }

    // ---- layer 3: 128 -> 2, warp reduce ----
    const float4 w3a = *(const float4*)(W3 + 8 * lane);
    const float4 w3b = *(const float4*)(W3 + 8 * lane + 4);
    const float b30 = b3[0], b31 = b3[1];

    float o0[8], o1[8];
    #pragma unroll
    for (int t = 0; t < 8; t++) {
        o0[t] = fmaf(h2[t][0], w3a.x, fmaf(h2[t][1], w3a.z,
                fmaf(h2[t][2], w3b.x, h2[t][3] * w3b.z)));
        o1[t] = fmaf(h2[t][0], w3a.y, fmaf(h2[t][1], w3a.w,
                fmaf(h2[t][2], w3b.y, h2[t][3] * w3b.w)));
    }
    #pragma unroll
    for (int off = 16; off; off >>= 1) {
        #pragma unroll
        for (int t = 0; t < 8; t++) {
            o0[t] += __shfl_xor_sync(0xFFFFFFFFu, o0[t], off);
            o1[t] += __shfl_xor_sync(0xFFFFFFFFu, o1[t], off);
        }
    }
    if (lane == 0) {
        #pragma unroll
        for (int t = 0; t < 8; t++) {
            float mu = gelu_exact(o0[t] + b30);
            float lv = gelu_exact(o1[t] + b31);
            float s = fmaxf(expf(0.5f * lv), 1e-8f);
            float inv = 1.0f / s;
            int j = t >> 1;
            float ts = x1[j], td = x0[j];
            // embed kc (6 bits) in low mantissa bits of ts
            unsigned tsb = (__float_as_uint(ts) & ~63u) | (unsigned)kcq[j];
            d_tab4[8 * gw + t] =
                make_float4(mu, inv * inv, __uint_as_float(tsb), ts * td);
        }
    }
}

// ---------------------------------------------------------------------------
// Kernel B: FUSED backward Mobius scan + forward KC scan, warp-per-user.
// kc decoded from ts_enc (no d_kcq gather: ~224 fewer wavefronts/warp).
// Phase 2: SIMD byte-match fast-skip (one __vcmpeq4 per 4-trial group).
// ---------------------------------------------------------------------------
__global__ void __launch_bounds__(256) scan_kernel(
    const int* __restrict__ q_id, const int* __restrict__ resp,
    float* __restrict__ out)
{
    const int lane = threadIdx.x & 31;
    const int wid  = threadIdx.x >> 5;
    const int u = blockIdx.x * 8 + wid;
    const int base = lane * 7;

    __shared__ float2 sbc[8][T_DIM];         // (b, c); m overwrites .x
    __shared__ unsigned int skcw[8][56];     // kc bytes (224 padded)
    __shared__ int sqr[8][224];              // 2*q+rs, then logits (reused)

    unsigned char* skc = (unsigned char*)&skcw[wid][0];

    // ---- phase 0: coalesced q/resp -> combined index in smem ----
    #pragma unroll
    for (int j = 0; j < 7; j++) {
        int t = j * 32 + lane;
        if (t < T_DIM) {
            int q  = q_id[u * T_DIM + t];
            int rs = resp[u * T_DIM + t];
            sqr[wid][t] = 2 * q + rs;
        }
    }
    __syncwarp();

    // ---- phase 1: gather packed trial records for owned segment ----
    float mu[7], rr[7], tsv[7], tdd[7];
    int kcv[7];
    #pragma unroll
    for (int j = 0; j < 7; j++) {
        int t = base + j;
        if (t < T_DIM) {
            int idx = sqr[wid][t];
            float4 f = d_tab4[idx];
            mu[j] = f.x; rr[j] = f.y; tsv[j] = f.z; tdd[j] = f.w;
            kcv[j] = __float_as_uint(f.z) & 63;   // kc from ts_enc
        } else {
            mu[j] = 0.0f; rr[j] = 0.0f; tsv[j] = 0.0f; tdd[j] = 0.0f; kcv[j] = 0;
        }
    }

    // ---- local product S = M_base * ... * M_{base+6} ----
    float m00 = 1.0f, m01 = 0.0f, m10 = 0.0f, m11 = 1.0f;
    float m20 = 0.0f, m21 = 0.0f, m22 = 1.0f;
    #pragma unroll
    for (int j = 6; j >= 0; j--) {
        if (base + j < T_DIM) {
            float a = 2.0f + rr[j];
            float g = rr[j] * mu[j];
            float n00 = m10,                n01 = m11;
            float n10 = fmaf(a, m10, -m00);
            float n11 = fmaf(a, m11, -m01);
            float n20 = fmaf(g, m10, m20);
            float n21 = fmaf(g, m11, m21);
            m00 = n00; m01 = n01; m10 = n10; m11 = n11;
            m20 = n20; m21 = n21;
        }
    }

    // ---- inclusive suffix scan (renormalized; q>0 invariant) ----
    #pragma unroll
    for (int d = 1; d < 32; d <<= 1) {
        float b00 = __shfl_down_sync(0xFFFFFFFFu, m00, d);
        float b01 = __shfl_down_sync(0xFFFFFFFFu, m01, d);
        float b10 = __shfl_down_sync(0xFFFFFFFFu, m10, d);
        float b11 = __shfl_down_sync(0xFFFFFFFFu, m11, d);
        float b20 = __shfl_down_sync(0xFFFFFFFFu, m20, d);
        float b21 = __shfl_down_sync(0xFFFFFFFFu, m21, d);
        float b22 = __shfl_down_sync(0xFFFFFFFFu, m22, d);
        if (lane + d < 32) {
            float c00 = fmaf(m00, b00, m01 * b10);
            float c01 = fmaf(m00, b01, m01 * b11);
            float c10 = fmaf(m10, b00, m11 * b10);
            float c11 = fmaf(m10, b01, m11 * b11);
            float c20 = fmaf(m20, b00, fmaf(m21, b10, m22 * b20));
            float c21 = fmaf(m20, b01, fmaf(m21, b11, m22 * b21));
            float c22 = m22 * b22;
            float s = __fdividef(1.0f, fabsf(c10) + fabsf(c11) + 1e-30f);
            m00 = c00 * s; m01 = c01 * s;
            m10 = c10 * s; m11 = c11 * s;
            m20 = c20 * s; m21 = c21 * s; m22 = c22 * s;
        }
    }

    // ---- exclusive carry: P_l = T_{l+1}; lane 31 -> identity ----
    float p00 = __shfl_down_sync(0xFFFFFFFFu, m00, 1);
    float p01 = __shfl_down_sync(0xFFFFFFFFu, m01, 1);
    float p10 = __shfl_down_sync(0xFFFFFFFFu, m10, 1);
    float p11 = __shfl_down_sync(0xFFFFFFFFu, m11, 1);
    float p20 = __shfl_down_sync(0xFFFFFFFFu, m20, 1);
    float p21 = __shfl_down_sync(0xFFFFFFFFu, m21, 1);
    if (lane == 31) {
        p00 = 1.0f; p01 = 0.0f; p10 = 0.0f; p11 = 1.0f; p20 = 0.0f; p21 = 0.0f;
    }

    float pp = p00 + p01;
    float qq = p10 + p11;
    float ww = p20 + p21;
    float invq = __fdividef(1.0f, qq);
    float b = pp * invq;
    float c = ww * invq;

    // ---- local replay (exact reference arithmetic), write to SMEM ----
    #pragma unroll
    for (int j = 6; j >= 0; j--) {
        int t = base + j;
        if (t < T_DIM) {
            float bn = __fdividef(1.0f, 2.0f + rr[j] - b);
            c = bn * fmaf(rr[j], mu[j], c);
            b = bn;
            sbc[wid][t] = make_float2(b, c);
            skc[t] = (unsigned char)kcv[j];
        }
    }
    __syncwarp();

    // ---- phase 2: forward scan, register KC state, vcmpeq fast-skip ----
    float s0 = 0.0f, s1 = 0.0f;
    const unsigned lrep = lane * 0x01010101u;
    #pragma unroll 5
    for (int g = 0; g < T_DIM / 4; g++) {
        unsigned kw = skcw[wid][g];                      // uniform LDS.32
        unsigned match = __vcmpeq4(kw & 0x1F1F1F1Fu, lrep);
        while (match) {
            int byte = (__ffs(match) - 1) >> 3;          // lowest t first
            int t = 4 * g + byte;
            int kj = (kw >> (8 * byte)) & 0xFF;
            float2 bc = sbc[wid][t];
            float s = (kj & 32) ? s1 : s0;
            float m = fmaf(bc.x, s, bc.y);
            if (kj & 32) s1 = m; else s0 = m;
            sbc[wid][t].x = m;                           // m overwrites b (dead)
            match &= ~(0xFFu << (8 * byte));
        }
    }
    __syncwarp();

    // ---- epilogue: logits staged to smem (sqr is dead), stored coalesced ----
    float* slog = (float*)&sqr[wid][0];
    #pragma unroll
    for (int j = 0; j < 7; j++) {
        int t = base + j;
        if (t < T_DIM) {
            float m = sbc[wid][t].x;
            slog[t] = fmaf(tsv[j], m, -tdd[j]);  // ts*m - ts*td
        }
    }
    __syncwarp();
    #pragma unroll
    for (int j = 0; j < 7; j++) {
        int t = j * 32 + lane;
        if (t < T_DIM) out[u * T_DIM + t] = slog[t];
    }

    // last_ability_kc: (U, K); lane owns k=lane (s0) and k=lane+32 (s1)
    float* o2 = out + (size_t)U_DIM * T_DIM + (size_t)u * K_DIM;
    o2[lane] = s0;
    o2[32 + lane] = s1;
}

// ---------------------------------------------------------------------------
// Launch
// ---------------------------------------------------------------------------
extern "C" void kernel_launch(void* const* d_in, const int* in_sizes, int n_in,
                              void* d_out, int out_size)
{
    // metadata order: mask, q_id, kmap, resp, diff_mu, disc_mu, W1,b1,W2,b2,W3,b3
    const int* q_id = (const int*)d_in[1];
    const int* kmap = (const int*)d_in[2];
    const int* resp = (const int*)d_in[3];
    const float* dmu = (const float*)d_in[4];
    const float* smu = (const float*)d_in[5];
    const float* W1 = (const float*)d_in[6];
    const float* b1 = (const float*)d_in[7];
    const float* W2 = (const float*)d_in[8];
    const float* b2 = (const float*)d_in[9];
    const float* W3 = (const float*)d_in[10];
    const float* b3 = (const float*)d_in[11];
    float* out = (float*)d_out;

    mlp_table_kernel<<<(Q_DIM / 4 + 3) / 4, 128>>>(dmu, smu, kmap,
                                                   W1, b1, W2, b2, W3, b3);
    scan_kernel<<<U_DIM / 8, 256>>>(q_id, resp, out);
}